// round 14
// baseline (speedup 1.0000x reference)
#include <cuda_runtime.h>
#include <math.h>

#define NNODES 100000
#define NPB 128
#define NBLK ((NNODES + NPB - 1) / NPB)   /* 782 */
#define NCLS 16
#define ECAP 1600000
#define SCANB 98                           /* ceil(100000/1024) */

typedef unsigned long long ull;

__device__ float  g_sums[NNODES * 64];     /* holds MEAN after gather */
__device__ float  g_cntf[NNODES];          /* fallback path only */
__device__ float  g_h[NNODES * 64];
__device__ float4 g_Wpack[2048];
__device__ float  g_bnsum[64];
__device__ float  g_bnsumsq[64];
__device__ int    g_flag;                  /* 1 = edge_index is int64 */
__device__ int    g_cnti[NNODES];
__device__ int    g_scan[NNODES];
__device__ int    g_rp[NNODES + 1];
__device__ int    g_blksum[SCANB];
__device__ int    g_blkoff[SCANB];
__device__ int    g_pos[ECAP];
__device__ int    g_csr[ECAP];

__device__ __forceinline__ ull fma2(ull a, ull b, ull c) {
    ull d; asm("fma.rn.f32x2 %0, %1, %2, %3;" : "=l"(d) : "l"(a), "l"(b), "l"(c)); return d;
}
__device__ __forceinline__ ull dup2(float v) {
    ull r; asm("mov.b64 %0, {%1, %1};" : "=l"(r) : "f"(v)); return r;
}
__device__ __forceinline__ float2 unp2(ull v) {
    float2 r; asm("mov.b64 {%0, %1}, %2;" : "=f"(r.x), "=f"(r.y) : "l"(v)); return r;
}
__device__ __forceinline__ int ld_src(const void* ei, int E, int e) {
    return g_flag ? (int)((const long long*)ei)[e] : ((const int*)ei)[e];
}
__device__ __forceinline__ int ld_dst(const void* ei, int E, int e) {
    return g_flag ? (int)((const long long*)ei)[(size_t)E + e] : ((const int*)ei)[E + e];
}

/* ---------------- prep: zero counters + detect idx width + pack W ---------------- */
__global__ void k_prep(const void* __restrict__ ei, const float* __restrict__ Wl,
                       const float* __restrict__ Wr) {
    int i = blockIdx.x * blockDim.x + threadIdx.x;
    int stride = gridDim.x * blockDim.x;
    for (int j = i; j < NNODES; j += stride) g_cnti[j] = 0;
    if (i < 64) { g_bnsum[i] = 0.f; g_bnsumsq[i] = 0.f; }

    if (blockIdx.x == 0 && threadIdx.x < 32) {
        const long long* p = (const long long*)ei;
        int bad = 0;
        for (int t = threadIdx.x; t < 128; t += 32) {
            long long v = p[t];
            if (v < 0 || v >= NNODES) bad = 1;
        }
        unsigned m = __ballot_sync(0xffffffffu, bad);
        if (threadIdx.x == 0) g_flag = (m == 0);
    }
    if (blockIdx.x == 1) {
        for (int t = threadIdx.x; t < 2048; t += 256) {
            int jpt = t >> 8, r = t & 255;
            int k = r >> 2, i2 = r & 3;
            int j = jpt * 8 + i2 * 2;
            g_Wpack[t] = make_float4(Wl[j * 64 + k], Wr[j * 64 + k],
                                     Wl[(j + 1) * 64 + k], Wr[(j + 1) * 64 + k]);
        }
    }
}

/* ---------------- hist: explicit 4-way batched (MLP4 on dst loads + atomics) ---------- */
__global__ __launch_bounds__(256) void k_hist(const void* __restrict__ ei, int E) {
    int T = gridDim.x * 256;
    int e0 = blockIdx.x * 256 + threadIdx.x;
    int e1 = e0 + T, e2 = e1 + T, e3 = e2 + T;
    if (e3 < E) {
        int d0 = ld_dst(ei, E, e0), d1 = ld_dst(ei, E, e1);
        int d2 = ld_dst(ei, E, e2), d3 = ld_dst(ei, E, e3);
        g_pos[e0] = atomicAdd(&g_cnti[d0], 1);
        g_pos[e1] = atomicAdd(&g_cnti[d1], 1);
        g_pos[e2] = atomicAdd(&g_cnti[d2], 1);
        g_pos[e3] = atomicAdd(&g_cnti[d3], 1);
    } else {
        for (int e = e0; e < E; e += T) {
            int dst = ld_dst(ei, E, e);
            g_pos[e] = atomicAdd(&g_cnti[dst], 1);
        }
    }
}

/* 98 blocks x 1024: warp-shfl inclusive scan + smem warp-total scan (2 syncs) */
__global__ __launch_bounds__(1024) void k_scan_blk() {
    __shared__ int wsum[32];
    int t = threadIdx.x, lane = t & 31, w = t >> 5;
    int i = blockIdx.x * 1024 + t;
    int v = (i < NNODES) ? g_cnti[i] : 0;
    int pre = v;
#pragma unroll
    for (int o = 1; o < 32; o <<= 1) {
        int u = __shfl_up_sync(0xffffffffu, pre, o);
        if (lane >= o) pre += u;
    }
    if (lane == 31) wsum[w] = pre;
    __syncthreads();
    if (t < 32) {
        int s = wsum[t];
#pragma unroll
        for (int o = 1; o < 32; o <<= 1) {
            int u = __shfl_up_sync(0xffffffffu, s, o);
            if (t >= o) s += u;
        }
        wsum[t] = s;
    }
    __syncthreads();
    int incl = pre + (w ? wsum[w - 1] : 0);
    if (i < NNODES) g_scan[i] = incl;
    if (t == 1023) g_blksum[blockIdx.x] = incl;
}

__global__ __launch_bounds__(128) void k_scan_top() {
    __shared__ int s[128];
    int t = threadIdx.x;
    int v = (t < SCANB) ? g_blksum[t] : 0;
    s[t] = v; __syncthreads();
#pragma unroll
    for (int o = 1; o < 128; o <<= 1) {
        int u = (t >= o) ? s[t - o] : 0;
        __syncthreads();
        if (t >= o) s[t] += u;
        __syncthreads();
    }
    if (t < SCANB) g_blkoff[t] = s[t] - v;   /* exclusive */
}

__global__ __launch_bounds__(1024) void k_scan_add() {
    int i = blockIdx.x * 1024 + threadIdx.x;
    if (i < NNODES) g_rp[i + 1] = g_scan[i] + g_blkoff[blockIdx.x];
    if (i == 0) g_rp[0] = 0;
}

/* ---------------- fill: explicit 4-way batched (all loads issued before stores) ------- */
__global__ __launch_bounds__(256) void k_fill(const void* __restrict__ ei, int E) {
    int T = gridDim.x * 256;
    int e0 = blockIdx.x * 256 + threadIdx.x;
    int e1 = e0 + T, e2 = e1 + T, e3 = e2 + T;
    if (e3 < E) {
        int s0 = ld_src(ei, E, e0), s1 = ld_src(ei, E, e1);
        int s2 = ld_src(ei, E, e2), s3 = ld_src(ei, E, e3);
        int d0 = ld_dst(ei, E, e0), d1 = ld_dst(ei, E, e1);
        int d2 = ld_dst(ei, E, e2), d3 = ld_dst(ei, E, e3);
        int r0 = g_rp[d0], r1 = g_rp[d1], r2 = g_rp[d2], r3 = g_rp[d3];
        int p0 = g_pos[e0], p1 = g_pos[e1], p2 = g_pos[e2], p3 = g_pos[e3];
        g_csr[r0 + p0] = s0;
        g_csr[r1 + p1] = s1;
        g_csr[r2 + p2] = s2;
        g_csr[r3 + p3] = s3;
    } else {
        for (int e = e0; e < E; e += T) {
            int src = ld_src(ei, E, e);
            int dst = ld_dst(ei, E, e);
            g_csr[g_rp[dst] + g_pos[e]] = src;
        }
    }
}

/* ---------------- gather: mean over neighbors, 16 lanes/node, MLP=4 ---------------- */
__global__ __launch_bounds__(256) void k_gather(const float* __restrict__ x) {
    int n = blockIdx.x * 16 + (threadIdx.x >> 4);
    if (n >= NNODES) return;
    int q = threadIdx.x & 15;
    int s = g_rp[n], e = g_rp[n + 1];
    int deg = e - s;
    const float4* xb = (const float4*)x;
    float4 acc0 = make_float4(0.f, 0.f, 0.f, 0.f);
    float4 acc1 = make_float4(0.f, 0.f, 0.f, 0.f);
    int i = s;
    for (; i + 3 < e; i += 4) {
        int s0 = g_csr[i], s1 = g_csr[i + 1], s2 = g_csr[i + 2], s3 = g_csr[i + 3];
        float4 a = __ldg(xb + (size_t)s0 * 16 + q);
        float4 b = __ldg(xb + (size_t)s1 * 16 + q);
        float4 c = __ldg(xb + (size_t)s2 * 16 + q);
        float4 d = __ldg(xb + (size_t)s3 * 16 + q);
        acc0.x += a.x; acc0.y += a.y; acc0.z += a.z; acc0.w += a.w;
        acc1.x += b.x; acc1.y += b.y; acc1.z += b.z; acc1.w += b.w;
        acc0.x += c.x; acc0.y += c.y; acc0.z += c.z; acc0.w += c.w;
        acc1.x += d.x; acc1.y += d.y; acc1.z += d.z; acc1.w += d.w;
    }
    if (i + 1 < e) {
        int s0 = g_csr[i], s1 = g_csr[i + 1];
        float4 a = __ldg(xb + (size_t)s0 * 16 + q);
        float4 b = __ldg(xb + (size_t)s1 * 16 + q);
        acc0.x += a.x; acc0.y += a.y; acc0.z += a.z; acc0.w += a.w;
        acc1.x += b.x; acc1.y += b.y; acc1.z += b.z; acc1.w += b.w;
        i += 2;
    }
    if (i < e) {
        float4 a = __ldg(xb + (size_t)g_csr[i] * 16 + q);
        acc0.x += a.x; acc0.y += a.y; acc0.z += a.z; acc0.w += a.w;
    }
    float rinv = __frcp_rn(fmaxf((float)deg, 1.0f));
    float4 m;
    m.x = (acc0.x + acc1.x) * rinv;
    m.y = (acc0.y + acc1.y) * rinv;
    m.z = (acc0.z + acc1.z) * rinv;
    m.w = (acc0.w + acc1.w) * rinv;
    ((float4*)g_sums)[(size_t)n * 16 + q] = m;
}

/* ---------------- fallback (E > ECAP): atomic scatter ---------------- */
__global__ void k_zero_fb() {
    int i = blockIdx.x * blockDim.x + threadIdx.x;
    int stride = gridDim.x * blockDim.x;
    float4 z = make_float4(0.f, 0.f, 0.f, 0.f);
    for (int j = i; j < NNODES * 16; j += stride) ((float4*)g_sums)[j] = z;
    for (int j = i; j < NNODES; j += stride) g_cntf[j] = 0.f;
}
__global__ __launch_bounds__(256) void k_edge_fb(const void* __restrict__ ei,
                                                 const float* __restrict__ x, int E) {
    int gw = (blockIdx.x * 256 + threadIdx.x) >> 5;
    int lane = threadIdx.x & 31;
    int e = gw * 2 + (lane >> 4);
    if (e >= E) return;
    int q = lane & 15;
    int src = ld_src(ei, E, e), dst = ld_dst(ei, E, e);
    float4 v = __ldg((const float4*)(x + (size_t)src * 64) + q);
    float* sp = g_sums + (size_t)dst * 64 + q * 4;
    asm volatile("red.global.add.v4.f32 [%0], {%1,%2,%3,%4};"
                 :: "l"(sp), "f"(v.x), "f"(v.y), "f"(v.z), "f"(v.w) : "memory");
    if (q == 0) atomicAdd(&g_cntf[dst], 1.0f);
}
__global__ __launch_bounds__(256) void k_meanize() {
    int n = blockIdx.x * 16 + (threadIdx.x >> 4);
    if (n >= NNODES) return;
    int q = threadIdx.x & 15;
    float rinv = __frcp_rn(fmaxf(g_cntf[n], 1.0f));
    float4 v = ((float4*)g_sums)[(size_t)n * 16 + q];
    v.x *= rinv; v.y *= rinv; v.z *= rinv; v.w *= rinv;
    ((float4*)g_sums)[(size_t)n * 16 + q] = v;
}

/* ---------------- GEMM1 fused: lin_l/lin_r + bias + L2norm + ReLU + BN stats ---------- */
__global__ __launch_bounds__(256, 2) void k_gemm1(const float* __restrict__ x,
                                                  const float* __restrict__ bl) {
    extern __shared__ float smem[];
    float2* sa = (float2*)smem;                    /* 66560 B */
    float4* sw = (float4*)(smem + 128 * 65 * 2);   /* 32896 B */
    int tid = threadIdx.x, lane = tid & 31, w = tid >> 5;

    for (int t = tid; t < 2048; t += 256) {
        int jpt = t >> 8, r = t & 255;
        sw[jpt * 257 + r] = g_Wpack[t];
    }

    {
        int nloc = w * 16 + (lane >> 1);
        int node = blockIdx.x * NPB + nloc;
        int khalf = (lane & 1) * 32;
        bool ok = node < NNODES;
        const float4* srow = (const float4*)(g_sums + (size_t)node * 64 + khalf);
        const float4* xrow = (const float4*)(x + (size_t)node * 64 + khalf);
        float2* dstp = sa + nloc * 65 + khalf;
        float4 zz = make_float4(0.f, 0.f, 0.f, 0.f);
#pragma unroll
        for (int q = 0; q < 8; q++) {
            float4 s4 = ok ? srow[q] : zz;
            float4 x4 = ok ? xrow[q] : zz;
            dstp[q * 4 + 0] = make_float2(s4.x, x4.x);
            dstp[q * 4 + 1] = make_float2(s4.y, x4.y);
            dstp[q * 4 + 2] = make_float2(s4.z, x4.z);
            dstp[q * 4 + 3] = make_float2(s4.w, x4.w);
        }
    }
    __syncthreads();

    int nt = lane & 3, jpt = lane >> 2;
    const float2* arow = sa + (w * 16 + nt * 4) * 65;
    const ulonglong2* wrow = (const ulonglong2*)(sw + jpt * 257);

    ull acc[4][8];
#pragma unroll
    for (int i = 0; i < 4; i++)
#pragma unroll
        for (int j = 0; j < 8; j++) acc[i][j] = 0ull;

#pragma unroll 16
    for (int k = 0; k < 64; k++) {
        ull a0 = *(const ull*)&arow[0 * 65 + k];
        ull a1 = *(const ull*)&arow[1 * 65 + k];
        ull a2 = *(const ull*)&arow[2 * 65 + k];
        ull a3 = *(const ull*)&arow[3 * 65 + k];
#pragma unroll
        for (int i2 = 0; i2 < 4; i2++) {
            ulonglong2 wv = wrow[k * 4 + i2];
            acc[0][i2 * 2 + 0] = fma2(a0, wv.x, acc[0][i2 * 2 + 0]);
            acc[0][i2 * 2 + 1] = fma2(a0, wv.y, acc[0][i2 * 2 + 1]);
            acc[1][i2 * 2 + 0] = fma2(a1, wv.x, acc[1][i2 * 2 + 0]);
            acc[1][i2 * 2 + 1] = fma2(a1, wv.y, acc[1][i2 * 2 + 1]);
            acc[2][i2 * 2 + 0] = fma2(a2, wv.x, acc[2][i2 * 2 + 0]);
            acc[2][i2 * 2 + 1] = fma2(a2, wv.y, acc[2][i2 * 2 + 1]);
            acc[3][i2 * 2 + 0] = fma2(a3, wv.x, acc[3][i2 * 2 + 0]);
            acc[3][i2 * 2 + 1] = fma2(a3, wv.y, acc[3][i2 * 2 + 1]);
        }
    }

    int jbase = jpt * 8;
    float bb[8];
    {
        float4 b0 = *(const float4*)(bl + jbase);
        float4 b1 = *(const float4*)(bl + jbase + 4);
        bb[0] = b0.x; bb[1] = b0.y; bb[2] = b0.z; bb[3] = b0.w;
        bb[4] = b1.x; bb[5] = b1.y; bb[6] = b1.z; bb[7] = b1.w;
    }
    float bns[8], bnq[8];
#pragma unroll
    for (int j = 0; j < 8; j++) { bns[j] = 0.f; bnq[j] = 0.f; }

    int nodebase = blockIdx.x * NPB + w * 16 + nt * 4;
#pragma unroll
    for (int i = 0; i < 4; i++) {
        float f[8]; float ss = 0.f;
#pragma unroll
        for (int j = 0; j < 8; j++) {
            float2 p = unp2(acc[i][j]);
            f[j] = p.x + p.y + bb[j];
            ss += f[j] * f[j];
        }
        ss += __shfl_xor_sync(0xffffffffu, ss, 4);
        ss += __shfl_xor_sync(0xffffffffu, ss, 8);
        ss += __shfl_xor_sync(0xffffffffu, ss, 16);
        float inv = 1.0f / fmaxf(sqrtf(ss), 1e-12f);
        int n = nodebase + i;
        if (n < NNODES) {
            float hv[8];
#pragma unroll
            for (int j = 0; j < 8; j++) {
                hv[j] = fmaxf(f[j] * inv, 0.f);
                bns[j] += hv[j]; bnq[j] += hv[j] * hv[j];
            }
            *(float4*)(g_h + (size_t)n * 64 + jbase)     = make_float4(hv[0], hv[1], hv[2], hv[3]);
            *(float4*)(g_h + (size_t)n * 64 + jbase + 4) = make_float4(hv[4], hv[5], hv[6], hv[7]);
        }
    }

    __syncthreads();
    float* bs = (float*)smem;
    float* bq = bs + 512;
#pragma unroll
    for (int j = 0; j < 8; j++) {
        float s = bns[j], q = bnq[j];
        s += __shfl_xor_sync(0xffffffffu, s, 1);
        s += __shfl_xor_sync(0xffffffffu, s, 2);
        q += __shfl_xor_sync(0xffffffffu, q, 1);
        q += __shfl_xor_sync(0xffffffffu, q, 2);
        if (nt == 0) { bs[w * 64 + jbase + j] = s; bq[w * 64 + jbase + j] = q; }
    }
    __syncthreads();
    if (tid < 64) {
        float s = 0.f, q = 0.f;
#pragma unroll
        for (int ww = 0; ww < 8; ww++) { s += bs[ww * 64 + tid]; q += bq[ww * 64 + tid]; }
        atomicAdd(&g_bnsum[tid], s);
        atomicAdd(&g_bnsumsq[tid], q);
    }
}

/* ---------------- GEMM2 v3: h row pre-loaded to registers (MLP=16), loads hoisted ------ */
__global__ __launch_bounds__(128) void k_gemm2(const float* __restrict__ gamma,
                                               const float* __restrict__ beta,
                                               const float* __restrict__ Wfc,
                                               const float* __restrict__ bfc,
                                               float* __restrict__ out) {
    __shared__ float4 sw2[64][4];
    __shared__ float  sc[64], sh[64];
    __shared__ float  sb2[16];
    int tid = threadIdx.x;
    int n = blockIdx.x * 128 + tid;
    bool ok = n < NNODES;

    float4 hreg[16];
    {
        const float4* hp = (const float4*)(g_h + (size_t)n * 64);
        float4 zz = make_float4(0.f, 0.f, 0.f, 0.f);
#pragma unroll
        for (int kc = 0; kc < 16; kc++) hreg[kc] = ok ? hp[kc] : zz;
    }

    if (tid < 64) {
        float mu  = g_bnsum[tid]   * (1.0f / (float)NNODES);
        float var = g_bnsumsq[tid] * (1.0f / (float)NNODES) - mu * mu;
        var = fmaxf(var, 0.f);
        float inv = rsqrtf(var + 1e-5f);
        float s = gamma[tid] * inv;
        sc[tid] = s; sh[tid] = beta[tid] - mu * s;
    }
    __syncthreads();
    for (int i = tid; i < 1024; i += 128) {
        int c = i >> 6, k = i & 63;
        ((float*)sw2)[k * 16 + c] = Wfc[i] * sc[k];
    }
    {
        int c = tid >> 3, j8 = tid & 7;
        float part = 0.f;
#pragma unroll
        for (int u = 0; u < 8; u++) {
            int k = j8 * 8 + u;
            part += sh[k] * Wfc[c * 64 + k];
        }
        part += __shfl_xor_sync(0xffffffffu, part, 1);
        part += __shfl_xor_sync(0xffffffffu, part, 2);
        part += __shfl_xor_sync(0xffffffffu, part, 4);
        if (j8 == 0) sb2[c] = part + bfc[c];
    }
    __syncthreads();

    if (!ok) return;

    ull acc[8];
#pragma unroll
    for (int i = 0; i < 8; i++) acc[i] = 0ull;

#pragma unroll
    for (int kc = 0; kc < 16; kc++) {
        float hk[4] = {hreg[kc].x, hreg[kc].y, hreg[kc].z, hreg[kc].w};
#pragma unroll
        for (int u = 0; u < 4; u++) {
            int k = kc * 4 + u;
            ull h2 = dup2(hk[u]);
            const ulonglong2* wp = (const ulonglong2*)&sw2[k][0];
            ulonglong2 w01 = wp[0], w23 = wp[1];
            acc[0] = fma2(h2, w01.x, acc[0]);
            acc[1] = fma2(h2, w01.y, acc[1]);
            acc[2] = fma2(h2, w23.x, acc[2]);
            acc[3] = fma2(h2, w23.y, acc[3]);
            ulonglong2 w45 = wp[2], w67 = wp[3];
            acc[4] = fma2(h2, w45.x, acc[4]);
            acc[5] = fma2(h2, w45.y, acc[5]);
            acc[6] = fma2(h2, w67.x, acc[6]);
            acc[7] = fma2(h2, w67.y, acc[7]);
        }
    }

    float o[16];
#pragma unroll
    for (int i = 0; i < 8; i++) {
        float2 p = unp2(acc[i]);
        o[2 * i]     = p.x + sb2[2 * i];
        o[2 * i + 1] = p.y + sb2[2 * i + 1];
    }
    float4* op = (float4*)(out + (size_t)n * 16);
    op[0] = make_float4(o[0], o[1], o[2], o[3]);
    op[1] = make_float4(o[4], o[5], o[6], o[7]);
    op[2] = make_float4(o[8], o[9], o[10], o[11]);
    op[3] = make_float4(o[12], o[13], o[14], o[15]);
}

extern "C" void kernel_launch(void* const* d_in, const int* in_sizes, int n_in,
                              void* d_out, int out_size) {
    const void*  ei    = d_in[0];
    const float* x     = (const float*)d_in[1];
    const float* Wl    = (const float*)d_in[2];
    const float* bl    = (const float*)d_in[3];
    const float* Wr    = (const float*)d_in[4];
    const float* gamma = (const float*)d_in[5];
    const float* beta  = (const float*)d_in[6];
    const float* Wfc   = (const float*)d_in[7];
    const float* bfc   = (const float*)d_in[8];
    int E = in_sizes[0] / 2;

    cudaFuncSetAttribute(k_gemm1, cudaFuncAttributeMaxDynamicSharedMemorySize, 99456);

    k_prep<<<512, 256>>>(ei, Wl, Wr);
    if (E <= ECAP) {
        k_hist<<<(E + 1023) / 1024, 256>>>(ei, E);
        k_scan_blk<<<SCANB, 1024>>>();
        k_scan_top<<<1, 128>>>();
        k_scan_add<<<SCANB, 1024>>>();
        k_fill<<<(E + 1023) / 1024, 256>>>(ei, E);
        k_gather<<<(NNODES + 15) / 16, 256>>>(x);
    } else {
        k_zero_fb<<<1024, 256>>>();
        k_edge_fb<<<(E + 15) / 16, 256>>>(ei, x, E);
        k_meanize<<<(NNODES + 15) / 16, 256>>>();
    }
    k_gemm1<<<NBLK, 256, 99456>>>(x, bl);
    k_gemm2<<<(NNODES + 127) / 128, 128>>>(gamma, beta, Wfc, bfc, (float*)d_out);
}

// round 15
// speedup vs baseline: 1.0066x; 1.0066x over previous
#include <cuda_runtime.h>
#include <math.h>

#define NNODES 100000
#define NPB 128
#define NBLK ((NNODES + NPB - 1) / NPB)   /* 782 */
#define NCLS 16
#define ECAP 1600000
#define SCANB 98                           /* ceil(100000/1024) */

typedef unsigned long long ull;

__device__ float  g_sums[NNODES * 64];     /* holds MEAN after gather */
__device__ float  g_cntf[NNODES];          /* fallback path only */
__device__ float  g_h[NNODES * 64];
__device__ float4 g_Wpack[2048];
__device__ float  g_bnsum[64];
__device__ float  g_bnsumsq[64];
__device__ int    g_flag;                  /* 1 = edge_index is int64 */
__device__ int    g_cnti[NNODES];
__device__ int    g_scan[NNODES];          /* inclusive per-block scan */
__device__ int    g_blksum[SCANB];
__device__ int    g_blkoff[SCANB];         /* exclusive block offsets */
__device__ int    g_pos[ECAP];
__device__ int    g_csr[ECAP];
__device__ int    g_rp_fb[NNODES + 1];     /* unused (kept for fallback symmetry) */

__device__ __forceinline__ ull fma2(ull a, ull b, ull c) {
    ull d; asm("fma.rn.f32x2 %0, %1, %2, %3;" : "=l"(d) : "l"(a), "l"(b), "l"(c)); return d;
}
__device__ __forceinline__ ull dup2(float v) {
    ull r; asm("mov.b64 %0, {%1, %1};" : "=l"(r) : "f"(v)); return r;
}
__device__ __forceinline__ float2 unp2(ull v) {
    float2 r; asm("mov.b64 {%0, %1}, %2;" : "=f"(r.x), "=f"(r.y) : "l"(v)); return r;
}
__device__ __forceinline__ int ld_src(const void* ei, int E, int e) {
    return g_flag ? (int)((const long long*)ei)[e] : ((const int*)ei)[e];
}
__device__ __forceinline__ int ld_dst(const void* ei, int E, int e) {
    return g_flag ? (int)((const long long*)ei)[(size_t)E + e] : ((const int*)ei)[E + e];
}
/* exclusive prefix (row_ptr) computed inline from scan + blkoff */
__device__ __forceinline__ int rp_of(int i) {   /* rp[i], 0 <= i <= NNODES */
    return i ? (g_scan[i - 1] + g_blkoff[(i - 1) >> 10]) : 0;
}

/* ---------------- prep: zero counters + detect idx width + pack W ---------------- */
__global__ void k_prep(const void* __restrict__ ei, const float* __restrict__ Wl,
                       const float* __restrict__ Wr) {
    int i = blockIdx.x * blockDim.x + threadIdx.x;
    int stride = gridDim.x * blockDim.x;
    for (int j = i; j < NNODES; j += stride) g_cnti[j] = 0;
    if (i < 64) { g_bnsum[i] = 0.f; g_bnsumsq[i] = 0.f; }

    if (blockIdx.x == 0 && threadIdx.x < 32) {
        const long long* p = (const long long*)ei;
        int bad = 0;
        for (int t = threadIdx.x; t < 128; t += 32) {
            long long v = p[t];
            if (v < 0 || v >= NNODES) bad = 1;
        }
        unsigned m = __ballot_sync(0xffffffffu, bad);
        if (threadIdx.x == 0) g_flag = (m == 0);
    }
    if (blockIdx.x == 1) {
        for (int t = threadIdx.x; t < 2048; t += 256) {
            int jpt = t >> 8, r = t & 255;
            int k = r >> 2, i2 = r & 3;
            int j = jpt * 8 + i2 * 2;
            g_Wpack[t] = make_float4(Wl[j * 64 + k], Wr[j * 64 + k],
                                     Wl[(j + 1) * 64 + k], Wr[(j + 1) * 64 + k]);
        }
    }
}

/* ---------------- CSR build: hist (saves slot) -> 2-step scan -> fill (inline rp) ----- */
__global__ __launch_bounds__(256) void k_hist(const void* __restrict__ ei, int E) {
    int e = blockIdx.x * 256 + threadIdx.x;
    if (e >= E) return;
    int dst = ld_dst(ei, E, e);
    g_pos[e] = atomicAdd(&g_cnti[dst], 1);
}

/* 98 blocks x 1024: warp-shfl inclusive scan + smem warp-total scan (2 syncs) */
__global__ __launch_bounds__(1024) void k_scan_blk() {
    __shared__ int wsum[32];
    int t = threadIdx.x, lane = t & 31, w = t >> 5;
    int i = blockIdx.x * 1024 + t;
    int v = (i < NNODES) ? g_cnti[i] : 0;
    int pre = v;
#pragma unroll
    for (int o = 1; o < 32; o <<= 1) {
        int u = __shfl_up_sync(0xffffffffu, pre, o);
        if (lane >= o) pre += u;
    }
    if (lane == 31) wsum[w] = pre;
    __syncthreads();
    if (t < 32) {
        int s = wsum[t];
#pragma unroll
        for (int o = 1; o < 32; o <<= 1) {
            int u = __shfl_up_sync(0xffffffffu, s, o);
            if (t >= o) s += u;
        }
        wsum[t] = s;
    }
    __syncthreads();
    int incl = pre + (w ? wsum[w - 1] : 0);
    if (i < NNODES) g_scan[i] = incl;
    if (t == 1023) g_blksum[blockIdx.x] = incl;
}

__global__ __launch_bounds__(128) void k_scan_top() {
    __shared__ int s[128];
    int t = threadIdx.x;
    int v = (t < SCANB) ? g_blksum[t] : 0;
    s[t] = v; __syncthreads();
#pragma unroll
    for (int o = 1; o < 128; o <<= 1) {
        int u = (t >= o) ? s[t - o] : 0;
        __syncthreads();
        if (t >= o) s[t] += u;
        __syncthreads();
    }
    if (t < SCANB) g_blkoff[t] = s[t] - v;   /* exclusive */
}

/* fill: grid-stride, rp computed inline (scan_add eliminated) */
__global__ __launch_bounds__(256) void k_fill(const void* __restrict__ ei, int E) {
    int T = gridDim.x * 256;
    for (int e = blockIdx.x * 256 + threadIdx.x; e < E; e += T) {
        int src = ld_src(ei, E, e);
        int dst = ld_dst(ei, E, e);
        g_csr[rp_of(dst) + g_pos[e]] = src;
    }
}

/* ---------------- gather: mean over neighbors, 16 lanes/node, MLP=4, inline rp -------- */
__global__ __launch_bounds__(256) void k_gather(const float* __restrict__ x) {
    int n = blockIdx.x * 16 + (threadIdx.x >> 4);
    if (n >= NNODES) return;
    int q = threadIdx.x & 15;
    int s = rp_of(n), e = rp_of(n + 1);
    int deg = e - s;
    const float4* xb = (const float4*)x;
    float4 acc0 = make_float4(0.f, 0.f, 0.f, 0.f);
    float4 acc1 = make_float4(0.f, 0.f, 0.f, 0.f);
    int i = s;
    for (; i + 3 < e; i += 4) {
        int s0 = g_csr[i], s1 = g_csr[i + 1], s2 = g_csr[i + 2], s3 = g_csr[i + 3];
        float4 a = __ldg(xb + (size_t)s0 * 16 + q);
        float4 b = __ldg(xb + (size_t)s1 * 16 + q);
        float4 c = __ldg(xb + (size_t)s2 * 16 + q);
        float4 d = __ldg(xb + (size_t)s3 * 16 + q);
        acc0.x += a.x; acc0.y += a.y; acc0.z += a.z; acc0.w += a.w;
        acc1.x += b.x; acc1.y += b.y; acc1.z += b.z; acc1.w += b.w;
        acc0.x += c.x; acc0.y += c.y; acc0.z += c.z; acc0.w += c.w;
        acc1.x += d.x; acc1.y += d.y; acc1.z += d.z; acc1.w += d.w;
    }
    if (i + 1 < e) {
        int s0 = g_csr[i], s1 = g_csr[i + 1];
        float4 a = __ldg(xb + (size_t)s0 * 16 + q);
        float4 b = __ldg(xb + (size_t)s1 * 16 + q);
        acc0.x += a.x; acc0.y += a.y; acc0.z += a.z; acc0.w += a.w;
        acc1.x += b.x; acc1.y += b.y; acc1.z += b.z; acc1.w += b.w;
        i += 2;
    }
    if (i < e) {
        float4 a = __ldg(xb + (size_t)g_csr[i] * 16 + q);
        acc0.x += a.x; acc0.y += a.y; acc0.z += a.z; acc0.w += a.w;
    }
    float rinv = __frcp_rn(fmaxf((float)deg, 1.0f));
    float4 m;
    m.x = (acc0.x + acc1.x) * rinv;
    m.y = (acc0.y + acc1.y) * rinv;
    m.z = (acc0.z + acc1.z) * rinv;
    m.w = (acc0.w + acc1.w) * rinv;
    ((float4*)g_sums)[(size_t)n * 16 + q] = m;
}

/* ---------------- fallback (E > ECAP): atomic scatter ---------------- */
__global__ void k_zero_fb() {
    int i = blockIdx.x * blockDim.x + threadIdx.x;
    int stride = gridDim.x * blockDim.x;
    float4 z = make_float4(0.f, 0.f, 0.f, 0.f);
    for (int j = i; j < NNODES * 16; j += stride) ((float4*)g_sums)[j] = z;
    for (int j = i; j < NNODES; j += stride) g_cntf[j] = 0.f;
}
__global__ __launch_bounds__(256) void k_edge_fb(const void* __restrict__ ei,
                                                 const float* __restrict__ x, int E) {
    int gw = (blockIdx.x * 256 + threadIdx.x) >> 5;
    int lane = threadIdx.x & 31;
    int e = gw * 2 + (lane >> 4);
    if (e >= E) return;
    int q = lane & 15;
    int src = ld_src(ei, E, e), dst = ld_dst(ei, E, e);
    float4 v = __ldg((const float4*)(x + (size_t)src * 64) + q);
    float* sp = g_sums + (size_t)dst * 64 + q * 4;
    asm volatile("red.global.add.v4.f32 [%0], {%1,%2,%3,%4};"
                 :: "l"(sp), "f"(v.x), "f"(v.y), "f"(v.z), "f"(v.w) : "memory");
    if (q == 0) atomicAdd(&g_cntf[dst], 1.0f);
}
__global__ __launch_bounds__(256) void k_meanize() {
    int n = blockIdx.x * 16 + (threadIdx.x >> 4);
    if (n >= NNODES) return;
    int q = threadIdx.x & 15;
    float rinv = __frcp_rn(fmaxf(g_cntf[n], 1.0f));
    float4 v = ((float4*)g_sums)[(size_t)n * 16 + q];
    v.x *= rinv; v.y *= rinv; v.z *= rinv; v.w *= rinv;
    ((float4*)g_sums)[(size_t)n * 16 + q] = v;
}

/* ---------------- GEMM1 fused: lin_l/lin_r + bias + L2norm + ReLU + BN stats ---------- */
__global__ __launch_bounds__(256, 2) void k_gemm1(const float* __restrict__ x,
                                                  const float* __restrict__ bl) {
    extern __shared__ float smem[];
    float2* sa = (float2*)smem;                    /* 66560 B */
    float4* sw = (float4*)(smem + 128 * 65 * 2);   /* 32896 B */
    int tid = threadIdx.x, lane = tid & 31, w = tid >> 5;

    for (int t = tid; t < 2048; t += 256) {
        int jpt = t >> 8, r = t & 255;
        sw[jpt * 257 + r] = g_Wpack[t];
    }

    {
        int nloc = w * 16 + (lane >> 1);
        int node = blockIdx.x * NPB + nloc;
        int khalf = (lane & 1) * 32;
        bool ok = node < NNODES;
        const float4* srow = (const float4*)(g_sums + (size_t)node * 64 + khalf);
        const float4* xrow = (const float4*)(x + (size_t)node * 64 + khalf);
        float2* dstp = sa + nloc * 65 + khalf;
        float4 zz = make_float4(0.f, 0.f, 0.f, 0.f);
#pragma unroll
        for (int q = 0; q < 8; q++) {
            float4 s4 = ok ? srow[q] : zz;
            float4 x4 = ok ? xrow[q] : zz;
            dstp[q * 4 + 0] = make_float2(s4.x, x4.x);
            dstp[q * 4 + 1] = make_float2(s4.y, x4.y);
            dstp[q * 4 + 2] = make_float2(s4.z, x4.z);
            dstp[q * 4 + 3] = make_float2(s4.w, x4.w);
        }
    }
    __syncthreads();

    int nt = lane & 3, jpt = lane >> 2;
    const float2* arow = sa + (w * 16 + nt * 4) * 65;
    const ulonglong2* wrow = (const ulonglong2*)(sw + jpt * 257);

    ull acc[4][8];
#pragma unroll
    for (int i = 0; i < 4; i++)
#pragma unroll
        for (int j = 0; j < 8; j++) acc[i][j] = 0ull;

#pragma unroll 16
    for (int k = 0; k < 64; k++) {
        ull a0 = *(const ull*)&arow[0 * 65 + k];
        ull a1 = *(const ull*)&arow[1 * 65 + k];
        ull a2 = *(const ull*)&arow[2 * 65 + k];
        ull a3 = *(const ull*)&arow[3 * 65 + k];
#pragma unroll
        for (int i2 = 0; i2 < 4; i2++) {
            ulonglong2 wv = wrow[k * 4 + i2];
            acc[0][i2 * 2 + 0] = fma2(a0, wv.x, acc[0][i2 * 2 + 0]);
            acc[0][i2 * 2 + 1] = fma2(a0, wv.y, acc[0][i2 * 2 + 1]);
            acc[1][i2 * 2 + 0] = fma2(a1, wv.x, acc[1][i2 * 2 + 0]);
            acc[1][i2 * 2 + 1] = fma2(a1, wv.y, acc[1][i2 * 2 + 1]);
            acc[2][i2 * 2 + 0] = fma2(a2, wv.x, acc[2][i2 * 2 + 0]);
            acc[2][i2 * 2 + 1] = fma2(a2, wv.y, acc[2][i2 * 2 + 1]);
            acc[3][i2 * 2 + 0] = fma2(a3, wv.x, acc[3][i2 * 2 + 0]);
            acc[3][i2 * 2 + 1] = fma2(a3, wv.y, acc[3][i2 * 2 + 1]);
        }
    }

    int jbase = jpt * 8;
    float bb[8];
    {
        float4 b0 = *(const float4*)(bl + jbase);
        float4 b1 = *(const float4*)(bl + jbase + 4);
        bb[0] = b0.x; bb[1] = b0.y; bb[2] = b0.z; bb[3] = b0.w;
        bb[4] = b1.x; bb[5] = b1.y; bb[6] = b1.z; bb[7] = b1.w;
    }
    float bns[8], bnq[8];
#pragma unroll
    for (int j = 0; j < 8; j++) { bns[j] = 0.f; bnq[j] = 0.f; }

    int nodebase = blockIdx.x * NPB + w * 16 + nt * 4;
#pragma unroll
    for (int i = 0; i < 4; i++) {
        float f[8]; float ss = 0.f;
#pragma unroll
        for (int j = 0; j < 8; j++) {
            float2 p = unp2(acc[i][j]);
            f[j] = p.x + p.y + bb[j];
            ss += f[j] * f[j];
        }
        ss += __shfl_xor_sync(0xffffffffu, ss, 4);
        ss += __shfl_xor_sync(0xffffffffu, ss, 8);
        ss += __shfl_xor_sync(0xffffffffu, ss, 16);
        float inv = 1.0f / fmaxf(sqrtf(ss), 1e-12f);
        int n = nodebase + i;
        if (n < NNODES) {
            float hv[8];
#pragma unroll
            for (int j = 0; j < 8; j++) {
                hv[j] = fmaxf(f[j] * inv, 0.f);
                bns[j] += hv[j]; bnq[j] += hv[j] * hv[j];
            }
            *(float4*)(g_h + (size_t)n * 64 + jbase)     = make_float4(hv[0], hv[1], hv[2], hv[3]);
            *(float4*)(g_h + (size_t)n * 64 + jbase + 4) = make_float4(hv[4], hv[5], hv[6], hv[7]);
        }
    }

    __syncthreads();
    float* bs = (float*)smem;
    float* bq = bs + 512;
#pragma unroll
    for (int j = 0; j < 8; j++) {
        float s = bns[j], q = bnq[j];
        s += __shfl_xor_sync(0xffffffffu, s, 1);
        s += __shfl_xor_sync(0xffffffffu, s, 2);
        q += __shfl_xor_sync(0xffffffffu, q, 1);
        q += __shfl_xor_sync(0xffffffffu, q, 2);
        if (nt == 0) { bs[w * 64 + jbase + j] = s; bq[w * 64 + jbase + j] = q; }
    }
    __syncthreads();
    if (tid < 64) {
        float s = 0.f, q = 0.f;
#pragma unroll
        for (int ww = 0; ww < 8; ww++) { s += bs[ww * 64 + tid]; q += bq[ww * 64 + tid]; }
        atomicAdd(&g_bnsum[tid], s);
        atomicAdd(&g_bnsumsq[tid], q);
    }
}

/* ---------------- GEMM2 v3: h row pre-loaded to registers (MLP=16), loads hoisted ------ */
__global__ __launch_bounds__(128) void k_gemm2(const float* __restrict__ gamma,
                                               const float* __restrict__ beta,
                                               const float* __restrict__ Wfc,
                                               const float* __restrict__ bfc,
                                               float* __restrict__ out) {
    __shared__ float4 sw2[64][4];
    __shared__ float  sc[64], sh[64];
    __shared__ float  sb2[16];
    int tid = threadIdx.x;
    int n = blockIdx.x * 128 + tid;
    bool ok = n < NNODES;

    float4 hreg[16];
    {
        const float4* hp = (const float4*)(g_h + (size_t)n * 64);
        float4 zz = make_float4(0.f, 0.f, 0.f, 0.f);
#pragma unroll
        for (int kc = 0; kc < 16; kc++) hreg[kc] = ok ? hp[kc] : zz;
    }

    if (tid < 64) {
        float mu  = g_bnsum[tid]   * (1.0f / (float)NNODES);
        float var = g_bnsumsq[tid] * (1.0f / (float)NNODES) - mu * mu;
        var = fmaxf(var, 0.f);
        float inv = rsqrtf(var + 1e-5f);
        float s = gamma[tid] * inv;
        sc[tid] = s; sh[tid] = beta[tid] - mu * s;
    }
    __syncthreads();
    for (int i = tid; i < 1024; i += 128) {
        int c = i >> 6, k = i & 63;
        ((float*)sw2)[k * 16 + c] = Wfc[i] * sc[k];
    }
    {
        int c = tid >> 3, j8 = tid & 7;
        float part = 0.f;
#pragma unroll
        for (int u = 0; u < 8; u++) {
            int k = j8 * 8 + u;
            part += sh[k] * Wfc[c * 64 + k];
        }
        part += __shfl_xor_sync(0xffffffffu, part, 1);
        part += __shfl_xor_sync(0xffffffffu, part, 2);
        part += __shfl_xor_sync(0xffffffffu, part, 4);
        if (j8 == 0) sb2[c] = part + bfc[c];
    }
    __syncthreads();

    if (!ok) return;

    ull acc[8];
#pragma unroll
    for (int i = 0; i < 8; i++) acc[i] = 0ull;

#pragma unroll
    for (int kc = 0; kc < 16; kc++) {
        float hk[4] = {hreg[kc].x, hreg[kc].y, hreg[kc].z, hreg[kc].w};
#pragma unroll
        for (int u = 0; u < 4; u++) {
            int k = kc * 4 + u;
            ull h2 = dup2(hk[u]);
            const ulonglong2* wp = (const ulonglong2*)&sw2[k][0];
            ulonglong2 w01 = wp[0], w23 = wp[1];
            acc[0] = fma2(h2, w01.x, acc[0]);
            acc[1] = fma2(h2, w01.y, acc[1]);
            acc[2] = fma2(h2, w23.x, acc[2]);
            acc[3] = fma2(h2, w23.y, acc[3]);
            ulonglong2 w45 = wp[2], w67 = wp[3];
            acc[4] = fma2(h2, w45.x, acc[4]);
            acc[5] = fma2(h2, w45.y, acc[5]);
            acc[6] = fma2(h2, w67.x, acc[6]);
            acc[7] = fma2(h2, w67.y, acc[7]);
        }
    }

    float o[16];
#pragma unroll
    for (int i = 0; i < 8; i++) {
        float2 p = unp2(acc[i]);
        o[2 * i]     = p.x + sb2[2 * i];
        o[2 * i + 1] = p.y + sb2[2 * i + 1];
    }
    float4* op = (float4*)(out + (size_t)n * 16);
    op[0] = make_float4(o[0], o[1], o[2], o[3]);
    op[1] = make_float4(o[4], o[5], o[6], o[7]);
    op[2] = make_float4(o[8], o[9], o[10], o[11]);
    op[3] = make_float4(o[12], o[13], o[14], o[15]);
}

extern "C" void kernel_launch(void* const* d_in, const int* in_sizes, int n_in,
                              void* d_out, int out_size) {
    const void*  ei    = d_in[0];
    const float* x     = (const float*)d_in[1];
    const float* Wl    = (const float*)d_in[2];
    const float* bl    = (const float*)d_in[3];
    const float* Wr    = (const float*)d_in[4];
    const float* gamma = (const float*)d_in[5];
    const float* beta  = (const float*)d_in[6];
    const float* Wfc   = (const float*)d_in[7];
    const float* bfc   = (const float*)d_in[8];
    int E = in_sizes[0] / 2;

    cudaFuncSetAttribute(k_gemm1, cudaFuncAttributeMaxDynamicSharedMemorySize, 99456);

    k_prep<<<512, 256>>>(ei, Wl, Wr);
    if (E <= ECAP) {
        k_hist<<<(E + 255) / 256, 256>>>(ei, E);
        k_scan_blk<<<SCANB, 1024>>>();
        k_scan_top<<<1, 128>>>();
        k_fill<<<(E + 1023) / 1024, 256>>>(ei, E);
        k_gather<<<(NNODES + 15) / 16, 256>>>(x);
    } else {
        k_zero_fb<<<1024, 256>>>();
        k_edge_fb<<<(E + 15) / 16, 256>>>(ei, x, E);
        k_meanize<<<(NNODES + 15) / 16, 256>>>();
    }
    k_gemm1<<<NBLK, 256, 99456>>>(x, bl);
    k_gemm2<<<(NNODES + 127) / 128, 128>>>(gamma, beta, Wfc, bfc, (float*)d_out);
}